// round 4
// baseline (speedup 1.0000x reference)
#include <cuda_runtime.h>
#include <math.h>

#define BATCH 512
#define H1_PER_B 8450   // 50*13*13
#define H2_PER_B 1250   // 50*5*5
#define L12_PER_B 8300  // 50*166
#define OUT_PER_B 6920  // 692*10

// ---------------- scratch (device globals; no runtime alloc) ----------------
__device__ float g_h1[BATCH * H1_PER_B];
__device__ float g_p7[BATCH * 50];
__device__ int   g_d1[BATCH];
__device__ float g_h2[BATCH * H2_PER_B];
__device__ int   g_d2[BATCH];
__device__ float g_c32[BATCH * 50];
__device__ float g_c3d[BATCH * H2_PER_B];
__device__ float g_l12[BATCH * L12_PER_B];
__device__ float g_A[10 * 500];
__device__ float g_C[10 * 500];

// ---------------- precompute affine l11-head factors ----------------
// A[s][m] = sum_k c1l1_w[s*50+k] * l1_w[m][k]
// C[s][m] = sum_k c1l1_b[s*50+k] * l1_w[m][k] + l1_b[m]
__global__ void k_precompAC(const float* __restrict__ c1l1w, const float* __restrict__ c1l1b,
                            const float* __restrict__ l1w, const float* __restrict__ l1b) {
    int s = blockIdx.x;       // 0..9
    int m = threadIdx.x;      // 0..499
    float a = 0.f, c = 0.f;
    const float* wrow = l1w + m * 50;
    #pragma unroll
    for (int k = 0; k < 50; k++) {
        float lw = wrow[k];
        a += c1l1w[s * 50 + k] * lw;
        c += c1l1b[s * 50 + k] * lw;
    }
    g_A[s * 500 + m] = a;
    g_C[s * 500 + m] = c + l1b[m];
}

// ---------------- conv 50->50 3x3 on 13x13 (+relu+pool2 -> 5x5), input in smem ----------------
__device__ __forceinline__ void conv50_pool(const float* __restrict__ s,
                                            const float* __restrict__ w,
                                            const float* __restrict__ bias,
                                            float* __restrict__ out, int tid) {
    if (tid < 250) {
        int c = tid / 5, py = tid % 5;
        float bc = bias[c];
        float acc[2][10];
        #pragma unroll
        for (int r = 0; r < 2; r++)
            #pragma unroll
            for (int xx = 0; xx < 10; xx++) acc[r][xx] = bc;
        const float* wc = w + c * 450;
        for (int ci = 0; ci < 50; ci++) {
            float win[4][12];
            const float* sc = s + ci * 169 + (2 * py) * 13;
            #pragma unroll
            for (int r = 0; r < 4; r++)
                #pragma unroll
                for (int xx = 0; xx < 12; xx++) win[r][xx] = sc[r * 13 + xx];
            float wv[9];
            #pragma unroll
            for (int k = 0; k < 9; k++) wv[k] = __ldg(wc + ci * 9 + k);
            #pragma unroll
            for (int r = 0; r < 2; r++)
                #pragma unroll
                for (int ky = 0; ky < 3; ky++)
                    #pragma unroll
                    for (int kx = 0; kx < 3; kx++)
                        #pragma unroll
                        for (int xx = 0; xx < 10; xx++)
                            acc[r][xx] += win[r + ky][xx + kx] * wv[ky * 3 + kx];
        }
        #pragma unroll
        for (int px = 0; px < 5; px++) {
            float m = fmaxf(fmaxf(acc[0][2 * px], acc[0][2 * px + 1]),
                            fmaxf(acc[1][2 * px], acc[1][2 * px + 1]));
            out[c * 25 + py * 5 + px] = fmaxf(m, 0.f);
        }
    }
}

// ---------------- fused stage 1+2: conv1+relu+pool2 -> h1, d1 argmax, pool7,
//                  conv2+relu+pool2 -> h2, d2 argmax. One block per sample. ----------------
__global__ void k_stage12(const float* __restrict__ x, const float* __restrict__ w1,
                          const float* __restrict__ b1,
                          const float* __restrict__ d1w, const float* __restrict__ d1b,
                          const float* __restrict__ w2, const float* __restrict__ b2,
                          const float* __restrict__ d2w, const float* __restrict__ d2b) {
    int b = blockIdx.x;
    int tid = threadIdx.x;
    __shared__ float sx[784];
    __shared__ float sw[450];
    __shared__ float sb[50];
    __shared__ float sh1[8450];
    __shared__ float sh2[1250];
    __shared__ int   sp7[50];          // channel max bits (values >= 0)
    __shared__ float r0[8], r1[8], r2[8];
    const float* xb = x + b * 784;
    for (int i = tid; i < 784; i += 256) sx[i] = xb[i];
    for (int i = tid; i < 450; i += 256) sw[i] = w1[i];
    for (int i = tid; i < 50; i += 256) { sb[i] = b1[i]; sp7[i] = 0; }
    __syncthreads();

    // ---- conv1 + relu + pool2, with fused d1 partial dots and p7 channel-max ----
    float* h1g = g_h1 + b * H1_PER_B;
    float a0 = 0.f, a1 = 0.f, a2 = 0.f;
    for (int o = tid; o < 8450; o += 256) {
        int c = o / 169, p = o % 169, py = p / 13, px = p % 13;
        const float* wc = sw + c * 9;
        float m = 0.f;  // pooled max of relu values (>=0)
        #pragma unroll
        for (int dy = 0; dy < 2; dy++) {
            #pragma unroll
            for (int dx = 0; dx < 2; dx++) {
                int cy = 2 * py + dy, cx = 2 * px + dx;
                float acc = sb[c];
                #pragma unroll
                for (int ky = 0; ky < 3; ky++)
                    #pragma unroll
                    for (int kx = 0; kx < 3; kx++)
                        acc += sx[(cy + ky) * 28 + cx + kx] * wc[ky * 3 + kx];
                m = fmaxf(m, acc);
            }
        }
        sh1[o] = m;
        h1g[o] = m;
        // d1 partial dots, same index order as the unfused kernel
        a0 += m * d1w[o];
        a1 += m * d1w[8450 + o];
        a2 += m * d1w[16900 + o];
        // pool7 window (y<7, x<7); values >= 0 so int-bit atomicMax is exact
        if (py < 7 && px < 7) atomicMax(&sp7[c], __float_as_int(m));
    }
    #pragma unroll
    for (int o = 16; o; o >>= 1) {
        a0 += __shfl_down_sync(0xffffffffu, a0, o);
        a1 += __shfl_down_sync(0xffffffffu, a1, o);
        a2 += __shfl_down_sync(0xffffffffu, a2, o);
    }
    if ((tid & 31) == 0) { r0[tid >> 5] = a0; r1[tid >> 5] = a1; r2[tid >> 5] = a2; }
    __syncthreads();
    if (tid == 0) {
        float l0 = d1b[0], l1 = d1b[1], l2 = d1b[2];
        for (int w_ = 0; w_ < 8; w_++) { l0 += r0[w_]; l1 += r1[w_]; l2 += r2[w_]; }
        int d = 0; float best = l0;
        if (l1 > best) { best = l1; d = 1; }
        if (l2 > best) { best = l2; d = 2; }
        g_d1[b] = d;
    }
    for (int c = tid; c < 50; c += 256)
        g_p7[b * 50 + c] = __int_as_float(sp7[c]);

    // ---- conv2 + relu + pool2 on smem-resident h1, then d2 ----
    conv50_pool(sh1, w2, b2, sh2, tid);
    __syncthreads();
    float* o2 = g_h2 + b * H2_PER_B;
    float c0 = 0.f, c1 = 0.f;
    for (int i = tid; i < 1250; i += 256) {
        float v = sh2[i];
        o2[i] = v;
        c0 += v * d2w[i];
        c1 += v * d2w[1250 + i];
    }
    #pragma unroll
    for (int off = 16; off; off >>= 1) {
        c0 += __shfl_down_sync(0xffffffffu, c0, off);
        c1 += __shfl_down_sync(0xffffffffu, c1, off);
    }
    if ((tid & 31) == 0) { r0[tid >> 5] = c0; r1[tid >> 5] = c1; }
    __syncthreads();
    if (tid == 0) {
        float s0 = d2b[0], s1 = d2b[1];
        for (int w_ = 0; w_ < 8; w_++) { s0 += r0[w_]; s1 += r1[w_]; }
        g_d2[b] = (s1 > s0) ? 1 : 0;
    }
}

// ---------------- branch d1==1: c33 = Linear(13->13) then conv3+relu+pool2 -> c3d ----------------
__global__ void k_c3d(const float* __restrict__ cw, const float* __restrict__ cb,
                      const float* __restrict__ w3, const float* __restrict__ b3) {
    int b = blockIdx.x;
    if (g_d1[b] != 1) return;
    int tid = threadIdx.x;
    __shared__ float s[8450];
    __shared__ float sw[169];
    __shared__ float sb2[13];
    if (tid < 169) sw[tid] = cw[tid];
    if (tid < 13) sb2[tid] = cb[tid];
    __syncthreads();
    const float* h = g_h1 + b * H1_PER_B;
    for (int o = tid; o < 8450; o += 256) {
        int row = o / 13, j = o % 13;     // row = c*13 + y
        const float* hr = h + row * 13;
        float a = sb2[j];
        #pragma unroll
        for (int k = 0; k < 13; k++) a += hr[k] * sw[j * 13 + k];
        s[o] = a;
    }
    __syncthreads();
    conv50_pool(s, w3, b3, g_c3d + b * H2_PER_B, tid);
}

// ---------------- branch d1==0,d2==0: conv3 on h2 (5x5) + relu + pool2 -> c32 [B,50] ----------------
__global__ void k_c32(const float* __restrict__ w3, const float* __restrict__ b3) {
    int b = blockIdx.x;
    if (g_d1[b] != 0 || g_d2[b] != 0) return;
    int tid = threadIdx.x;
    __shared__ float s2[1250];
    for (int i = tid; i < 1250; i += 64) s2[i] = g_h2[b * H2_PER_B + i];
    __syncthreads();
    if (tid < 50) {
        int c = tid;
        float bc = b3[c];
        float acc[2][2];
        acc[0][0] = acc[0][1] = acc[1][0] = acc[1][1] = bc;
        const float* wc = w3 + c * 450;
        for (int ci = 0; ci < 50; ci++) {
            float win[4][4];
            const float* sc = s2 + ci * 25;
            #pragma unroll
            for (int r = 0; r < 4; r++)
                #pragma unroll
                for (int xx = 0; xx < 4; xx++) win[r][xx] = sc[r * 5 + xx];
            float wv[9];
            #pragma unroll
            for (int k = 0; k < 9; k++) wv[k] = __ldg(wc + ci * 9 + k);
            #pragma unroll
            for (int py = 0; py < 2; py++)
                #pragma unroll
                for (int px = 0; px < 2; px++)
                    #pragma unroll
                    for (int ky = 0; ky < 3; ky++)
                        #pragma unroll
                        for (int kx = 0; kx < 3; kx++)
                            acc[py][px] += win[py + ky][px + kx] * wv[ky * 3 + kx];
        }
        float m = fmaxf(fmaxf(acc[0][0], acc[0][1]), fmaxf(acc[1][0], acc[1][1]));
        g_c32[b * 50 + c] = fmaxf(m, 0.f);
    }
}

// ---------------- branch d1==0,d2==1: Linear(5->500) + pool(3,3) -> l12 [B,50,166] ----------------
__global__ void k_l12(const float* __restrict__ w, const float* __restrict__ bias) {
    int b = blockIdx.x;
    if (g_d1[b] != 0 || g_d2[b] != 1) return;
    int tid = threadIdx.x;
    __shared__ float s2[1250];
    __shared__ float sw[2500];
    __shared__ float sb[500];
    for (int i = tid; i < 1250; i += 256) s2[i] = g_h2[b * H2_PER_B + i];
    for (int i = tid; i < 2500; i += 256) sw[i] = w[i];
    for (int i = tid; i < 500; i += 256) sb[i] = bias[i];
    __syncthreads();
    for (int o = tid; o < L12_PER_B; o += 256) {
        int c = o / 166, t = o % 166;
        const float* hc = s2 + c * 25;
        float m = -1e30f;
        #pragma unroll
        for (int i = 0; i < 3; i++) {
            #pragma unroll
            for (int dj = 0; dj < 3; dj++) {
                int j = 3 * t + dj;
                float a = sb[j];
                #pragma unroll
                for (int k = 0; k < 5; k++) a += hc[i * 5 + k] * sw[j * 5 + k];
                m = fmaxf(m, a);
            }
        }
        g_l12[b * L12_PER_B + o] = m;
    }
}

// ---------------- l11 head (affine trick): rows 0..499, gate d1==2 ----------------
__global__ void k_head_l11(const float* __restrict__ l2w, const float* __restrict__ l2b,
                           float* __restrict__ out) {
    int b = blockIdx.y;
    if (g_d1[b] != 2) return;
    int tid = threadIdx.x, lane = tid & 31, r = tid >> 5;   // 8 rows/block
    int gr = blockIdx.x * 8 + r;
    __shared__ float sl2[500 * 11];
    __shared__ float slog[8][10];
    for (int i = tid; i < 5000; i += 256) {
        int m = i / 10, l = i % 10;
        sl2[m * 11 + l] = l2w[l * 500 + m];
    }
    __syncthreads();
    bool act = (gr < 500);
    int s_ = act ? (gr % 10) : 0;
    int c_ = act ? (gr / 10) : 0;
    float p = act ? g_p7[b * 50 + c_] : 0.f;
    const float* Ap = g_A + s_ * 500;
    const float* Cp = g_C + s_ * 500;
    float acc[10];
    #pragma unroll
    for (int l = 0; l < 10; l++) acc[l] = 0.f;
    for (int m = lane; m < 500; m += 32) {
        float h = fmaxf(fmaf(p, __ldg(Ap + m), __ldg(Cp + m)), 0.f);
        #pragma unroll
        for (int l = 0; l < 10; l++) acc[l] += h * sl2[m * 11 + l];
    }
    #pragma unroll
    for (int off = 16; off; off >>= 1)
        #pragma unroll
        for (int l = 0; l < 10; l++) acc[l] += __shfl_down_sync(0xffffffffu, acc[l], off);
    if (lane == 0) {
        #pragma unroll
        for (int l = 0; l < 10; l++) slog[r][l] = acc[l] + l2b[l];
    }
    __syncthreads();
    if (tid < 8) {
        int grr = blockIdx.x * 8 + tid;
        if (grr < 500) {
            float z[10], mx = -1e30f;
            #pragma unroll
            for (int l = 0; l < 10; l++) { z[l] = slog[tid][l]; mx = fmaxf(mx, z[l]); }
            float se = 0.f;
            #pragma unroll
            for (int l = 0; l < 10; l++) se += expf(z[l] - mx);
            float lse = mx + logf(se);
            float* o = out + (size_t)b * OUT_PER_B + grr * 10;
            #pragma unroll
            for (int l = 0; l < 10; l++) o[l] = z[l] - lse;
        }
    }
}

// ---------------- generic head: sel 0=l12, 1=c32, 2=c3d ----------------
__global__ void k_head_gen(int sel, int nrows, int rowbase, int gd1, int gd2,
                           const float* __restrict__ l1w, const float* __restrict__ l1b,
                           const float* __restrict__ l2w, const float* __restrict__ l2b,
                           float* __restrict__ out) {
    int b = blockIdx.y;
    if (g_d1[b] != gd1) return;
    if (gd2 >= 0 && g_d2[b] != gd2) return;
    const float* src;
    int perb;
    if (sel == 0)      { src = g_l12; perb = L12_PER_B; }
    else if (sel == 1) { src = g_c32; perb = 50; }
    else               { src = g_c3d; perb = H2_PER_B; }

    int tid = threadIdx.x, lane = tid & 31, r = tid >> 5;
    int gr = blockIdx.x * 8 + r;
    __shared__ float sl2[500 * 11];   // l2_w transposed, stride 11 (conflict-free)
    __shared__ float sl1c[64 * 51];   // l1_w chunk, stride 51 (conflict-free)
    __shared__ float sbias[500];
    __shared__ float sv[8][50];
    __shared__ float slog[8][10];
    for (int i = tid; i < 5000; i += 256) {
        int m = i / 10, l = i % 10;
        sl2[m * 11 + l] = l2w[l * 500 + m];
    }
    for (int i = tid; i < 500; i += 256) sbias[i] = l1b[i];
    int rows_here = nrows - blockIdx.x * 8;
    if (rows_here > 8) rows_here = 8;
    for (int i = tid; i < 400; i += 256) {
        int rr = i / 50, k = i % 50;
        sv[rr][k] = (rr < rows_here)
            ? src[(size_t)b * perb + (blockIdx.x * 8 + rr) * 50 + k] : 0.f;
    }
    __syncthreads();
    float vr[50];
    #pragma unroll
    for (int k = 0; k < 50; k++) vr[k] = sv[r][k];
    float acc[10];
    #pragma unroll
    for (int l = 0; l < 10; l++) acc[l] = 0.f;
    for (int m0 = 0; m0 < 500; m0 += 64) {
        int cnt = 500 - m0; if (cnt > 64) cnt = 64;
        __syncthreads();
        for (int i = tid; i < cnt * 50; i += 256) {
            int mm = i / 50, k = i % 50;
            sl1c[mm * 51 + k] = l1w[(m0 + mm) * 50 + k];
        }
        __syncthreads();
        for (int mm = lane; mm < cnt; mm += 32) {
            int m = m0 + mm;
            float h = sbias[m];
            const float* wrow = sl1c + mm * 51;
            #pragma unroll
            for (int k = 0; k < 50; k++) h += vr[k] * wrow[k];
            h = fmaxf(h, 0.f);
            #pragma unroll
            for (int l = 0; l < 10; l++) acc[l] += h * sl2[m * 11 + l];
        }
    }
    #pragma unroll
    for (int off = 16; off; off >>= 1)
        #pragma unroll
        for (int l = 0; l < 10; l++) acc[l] += __shfl_down_sync(0xffffffffu, acc[l], off);
    if (lane == 0) {
        #pragma unroll
        for (int l = 0; l < 10; l++) slog[r][l] = acc[l] + l2b[l];
    }
    __syncthreads();
    if (tid < 8) {
        int grr = blockIdx.x * 8 + tid;
        if (grr < nrows) {
            float z[10], mx = -1e30f;
            #pragma unroll
            for (int l = 0; l < 10; l++) { z[l] = slog[tid][l]; mx = fmaxf(mx, z[l]); }
            float se = 0.f;
            #pragma unroll
            for (int l = 0; l < 10; l++) se += expf(z[l] - mx);
            float lse = mx + logf(se);
            float* o = out + (size_t)b * OUT_PER_B + (rowbase + grr) * 10;
            #pragma unroll
            for (int l = 0; l < 10; l++) o[l] = z[l] - lse;
        }
    }
}

// ---------------- optional d1/d2 outputs (cast to float) ----------------
__global__ void k_write_dx(float* __restrict__ out, int wd1, int wd2) {
    int i = blockIdx.x * blockDim.x + threadIdx.x;
    if (i < BATCH) {
        if (wd1) out[(size_t)BATCH * OUT_PER_B + i] = (float)g_d1[i];
        if (wd2) out[(size_t)BATCH * OUT_PER_B + BATCH + i] = (float)g_d2[i];
    }
}

extern "C" void kernel_launch(void* const* d_in, const int* in_sizes, int n_in,
                              void* d_out, int out_size) {
    const float* x     = (const float*)d_in[0];
    const float* c1w   = (const float*)d_in[1];
    const float* c1b   = (const float*)d_in[2];
    const float* c2w   = (const float*)d_in[3];
    const float* c2b   = (const float*)d_in[4];
    const float* c3w   = (const float*)d_in[5];
    const float* c3b   = (const float*)d_in[6];
    const float* l1w   = (const float*)d_in[7];
    const float* l1b   = (const float*)d_in[8];
    const float* l2w   = (const float*)d_in[9];
    const float* l2b   = (const float*)d_in[10];
    const float* d1w   = (const float*)d_in[11];
    const float* d1b   = (const float*)d_in[12];
    const float* d2w   = (const float*)d_in[13];
    const float* d2b   = (const float*)d_in[14];
    const float* c1c3w = (const float*)d_in[15];
    const float* c1c3b = (const float*)d_in[16];
    const float* c1l1w = (const float*)d_in[17];
    const float* c1l1b = (const float*)d_in[18];
    const float* c2l1w = (const float*)d_in[19];
    const float* c2l1b = (const float*)d_in[20];
    float* out = (float*)d_out;

    cudaMemsetAsync(d_out, 0, (size_t)out_size * sizeof(float), 0);

    k_precompAC<<<10, 500>>>(c1l1w, c1l1b, l1w, l1b);
    k_stage12<<<BATCH, 256>>>(x, c1w, c1b, d1w, d1b, c2w, c2b, d2w, d2b);
    k_c3d<<<BATCH, 256>>>(c1c3w, c1c3b, c3w, c3b);
    k_c32<<<BATCH, 64>>>(c3w, c3b);
    k_l12<<<BATCH, 256>>>(c2l1w, c2l1b);

    // heads (out rows: l11 0..499 | l12 500..665 | c32 666 | c3d 667..691)
    k_head_l11<<<dim3(63, BATCH), 256>>>(l2w, l2b, out);
    k_head_gen<<<dim3(21, BATCH), 256>>>(0, 166, 500, 0, 1, l1w, l1b, l2w, l2b, out);
    k_head_gen<<<dim3(1,  BATCH), 256>>>(1, 1,   666, 0, 0, l1w, l1b, l2w, l2b, out);
    k_head_gen<<<dim3(4,  BATCH), 256>>>(2, 25,  667, 1, -1, l1w, l1b, l2w, l2b, out);

    long long base = (long long)BATCH * OUT_PER_B;
    int wd1 = (out_size >= base + BATCH) ? 1 : 0;
    int wd2 = (out_size >= base + 2 * BATCH) ? 1 : 0;
    if (wd1 || wd2) k_write_dx<<<2, 256>>>(out, wd1, wd2);
}

// round 8
// speedup vs baseline: 1.0046x; 1.0046x over previous
#include <cuda_runtime.h>
#include <math.h>

#define BATCH 512
#define H1_PER_B 8450   // 50*13*13
#define H2_PER_B 1250   // 50*5*5
#define L12_PER_B 8300  // 50*166
#define OUT_PER_B 6920  // 692*10

// ---------------- scratch (device globals; no runtime alloc) ----------------
__device__ float g_h1[BATCH * H1_PER_B];
__device__ float g_p7[BATCH * 50];
__device__ int   g_d1[BATCH];
__device__ float g_h2[BATCH * H2_PER_B];
__device__ int   g_d2[BATCH];
__device__ float g_c32[BATCH * 50];
__device__ float g_c3d[BATCH * H2_PER_B];
__device__ float g_l12[BATCH * L12_PER_B];
__device__ float g_A[10 * 500];
__device__ float g_C[10 * 500];

// ---------------- precompute affine l11-head factors ----------------
__global__ void k_precompAC(const float* __restrict__ c1l1w, const float* __restrict__ c1l1b,
                            const float* __restrict__ l1w, const float* __restrict__ l1b) {
    int s = blockIdx.x;       // 0..9
    int m = threadIdx.x;      // 0..499
    float a = 0.f, c = 0.f;
    const float* wrow = l1w + m * 50;
    #pragma unroll
    for (int k = 0; k < 50; k++) {
        float lw = wrow[k];
        a += c1l1w[s * 50 + k] * lw;
        c += c1l1b[s * 50 + k] * lw;
    }
    g_A[s * 500 + m] = a;
    g_C[s * 500 + m] = c + l1b[m];
}

// ---------------- conv 50->50 3x3 on 13x13 (+relu+pool2 -> 5x5), input in smem ----------------
__device__ __forceinline__ void conv50_pool(const float* __restrict__ s,
                                            const float* __restrict__ w,
                                            const float* __restrict__ bias,
                                            float* __restrict__ out, int tid) {
    if (tid < 250) {
        int c = tid / 5, py = tid % 5;
        float bc = bias[c];
        float acc[2][10];
        #pragma unroll
        for (int r = 0; r < 2; r++)
            #pragma unroll
            for (int xx = 0; xx < 10; xx++) acc[r][xx] = bc;
        const float* wc = w + c * 450;
        for (int ci = 0; ci < 50; ci++) {
            float win[4][12];
            const float* sc = s + ci * 169 + (2 * py) * 13;
            #pragma unroll
            for (int r = 0; r < 4; r++)
                #pragma unroll
                for (int xx = 0; xx < 12; xx++) win[r][xx] = sc[r * 13 + xx];
            float wv[9];
            #pragma unroll
            for (int k = 0; k < 9; k++) wv[k] = __ldg(wc + ci * 9 + k);
            #pragma unroll
            for (int r = 0; r < 2; r++)
                #pragma unroll
                for (int ky = 0; ky < 3; ky++)
                    #pragma unroll
                    for (int kx = 0; kx < 3; kx++)
                        #pragma unroll
                        for (int xx = 0; xx < 10; xx++)
                            acc[r][xx] += win[r + ky][xx + kx] * wv[ky * 3 + kx];
        }
        #pragma unroll
        for (int px = 0; px < 5; px++) {
            float m = fmaxf(fmaxf(acc[0][2 * px], acc[0][2 * px + 1]),
                            fmaxf(acc[1][2 * px], acc[1][2 * px + 1]));
            out[c * 25 + py * 5 + px] = fmaxf(m, 0.f);
        }
    }
}

// ---------------- fused stage 1+2: conv1+relu+pool2, d1, pool7, conv2+relu+pool2, d2 ----------------
__global__ void __launch_bounds__(256) k_stage12(
        const float* __restrict__ x, const float* __restrict__ w1,
        const float* __restrict__ b1,
        const float* __restrict__ d1w, const float* __restrict__ d1b,
        const float* __restrict__ w2, const float* __restrict__ b2,
        const float* __restrict__ d2w, const float* __restrict__ d2b) {
    int b = blockIdx.x;
    int tid = threadIdx.x;
    __shared__ float sx[784];
    __shared__ float sw[450];
    __shared__ float sb[50];
    __shared__ float sh1[8450];
    __shared__ float sh2[1250];
    __shared__ int   sp7[50];          // channel max bits (values >= 0)
    __shared__ float r0[8], r1[8], r2[8];
    const float* xb = x + b * 784;
    for (int i = tid; i < 784; i += 256) sx[i] = xb[i];
    for (int i = tid; i < 450; i += 256) sw[i] = w1[i];
    for (int i = tid; i < 50; i += 256) { sb[i] = b1[i]; sp7[i] = 0; }
    __syncthreads();

    float* h1g = g_h1 + b * H1_PER_B;
    float a0 = 0.f, a1 = 0.f, a2 = 0.f;
    for (int o = tid; o < 8450; o += 256) {
        int c = o / 169, p = o % 169, py = p / 13, px = p % 13;
        const float* wc = sw + c * 9;
        float m = 0.f;
        #pragma unroll
        for (int dy = 0; dy < 2; dy++) {
            #pragma unroll
            for (int dx = 0; dx < 2; dx++) {
                int cy = 2 * py + dy, cx = 2 * px + dx;
                float acc = sb[c];
                #pragma unroll
                for (int ky = 0; ky < 3; ky++)
                    #pragma unroll
                    for (int kx = 0; kx < 3; kx++)
                        acc += sx[(cy + ky) * 28 + cx + kx] * wc[ky * 3 + kx];
                m = fmaxf(m, acc);
            }
        }
        sh1[o] = m;
        h1g[o] = m;
        a0 += m * d1w[o];
        a1 += m * d1w[8450 + o];
        a2 += m * d1w[16900 + o];
        if (py < 7 && px < 7) atomicMax(&sp7[c], __float_as_int(m));
    }
    #pragma unroll
    for (int o = 16; o; o >>= 1) {
        a0 += __shfl_down_sync(0xffffffffu, a0, o);
        a1 += __shfl_down_sync(0xffffffffu, a1, o);
        a2 += __shfl_down_sync(0xffffffffu, a2, o);
    }
    if ((tid & 31) == 0) { r0[tid >> 5] = a0; r1[tid >> 5] = a1; r2[tid >> 5] = a2; }
    __syncthreads();
    if (tid == 0) {
        float l0 = d1b[0], l1 = d1b[1], l2 = d1b[2];
        for (int w_ = 0; w_ < 8; w_++) { l0 += r0[w_]; l1 += r1[w_]; l2 += r2[w_]; }
        int d = 0; float best = l0;
        if (l1 > best) { best = l1; d = 1; }
        if (l2 > best) { best = l2; d = 2; }
        g_d1[b] = d;
    }
    for (int c = tid; c < 50; c += 256)
        g_p7[b * 50 + c] = __int_as_float(sp7[c]);

    conv50_pool(sh1, w2, b2, sh2, tid);
    __syncthreads();
    float* o2 = g_h2 + b * H2_PER_B;
    float c0 = 0.f, c1 = 0.f;
    for (int i = tid; i < 1250; i += 256) {
        float v = sh2[i];
        o2[i] = v;
        c0 += v * d2w[i];
        c1 += v * d2w[1250 + i];
    }
    #pragma unroll
    for (int off = 16; off; off >>= 1) {
        c0 += __shfl_down_sync(0xffffffffu, c0, off);
        c1 += __shfl_down_sync(0xffffffffu, c1, off);
    }
    if ((tid & 31) == 0) { r0[tid >> 5] = c0; r1[tid >> 5] = c1; }
    __syncthreads();
    if (tid == 0) {
        float s0 = d2b[0], s1 = d2b[1];
        for (int w_ = 0; w_ < 8; w_++) { s0 += r0[w_]; s1 += r1[w_]; }
        g_d2[b] = (s1 > s0) ? 1 : 0;
    }
}

// ---------------- merged branch kernel: per sample exactly one of c3d / c32 / l12 ----------------
__global__ void __launch_bounds__(256) k_branch(
        const float* __restrict__ cw, const float* __restrict__ cb,     // c1c3 (13->13)
        const float* __restrict__ w3, const float* __restrict__ b3,     // conv3
        const float* __restrict__ lw, const float* __restrict__ lb) {   // c2l1 (5->500)
    int b = blockIdx.x;
    int tid = threadIdx.x;
    int d1 = g_d1[b];
    if (d1 == 2) return;

    if (d1 == 1) {
        // ---- c3d: Linear(13->13) on h1 rows, conv3+relu+pool2 -> g_c3d ----
        __shared__ float s[8450];
        __shared__ float swl[169];
        __shared__ float sbl[13];
        if (tid < 169) swl[tid] = cw[tid];
        if (tid < 13) sbl[tid] = cb[tid];
        __syncthreads();
        const float* h = g_h1 + b * H1_PER_B;
        for (int o = tid; o < 8450; o += 256) {
            int row = o / 13, j = o % 13;
            const float* hr = h + row * 13;
            float a = sbl[j];
            #pragma unroll
            for (int k = 0; k < 13; k++) a += hr[k] * swl[j * 13 + k];
            s[o] = a;
        }
        __syncthreads();
        conv50_pool(s, w3, b3, g_c3d + b * H2_PER_B, tid);
        return;
    }

    // d1 == 0 paths need h2 in smem
    __shared__ float s2[1250];
    for (int i = tid; i < 1250; i += 256) s2[i] = g_h2[b * H2_PER_B + i];

    if (g_d2[b] == 0) {
        // ---- c32: conv3 on 5x5 + relu + pool2 -> [50]; ci split over 5 groups ----
        __shared__ float part[50 * 5 * 4];
        __syncthreads();
        if (tid < 250) {
            int c = tid / 5, g = tid % 5;
            float acc[2][2];
            acc[0][0] = acc[0][1] = acc[1][0] = acc[1][1] = 0.f;
            const float* wc = w3 + c * 450;
            for (int ci = g * 10; ci < g * 10 + 10; ci++) {
                float win[4][4];
                const float* sc = s2 + ci * 25;
                #pragma unroll
                for (int r = 0; r < 4; r++)
                    #pragma unroll
                    for (int xx = 0; xx < 4; xx++) win[r][xx] = sc[r * 5 + xx];
                float wv[9];
                #pragma unroll
                for (int k = 0; k < 9; k++) wv[k] = __ldg(wc + ci * 9 + k);
                #pragma unroll
                for (int py = 0; py < 2; py++)
                    #pragma unroll
                    for (int px = 0; px < 2; px++)
                        #pragma unroll
                        for (int ky = 0; ky < 3; ky++)
                            #pragma unroll
                            for (int kx = 0; kx < 3; kx++)
                                acc[py][px] += win[py + ky][px + kx] * wv[ky * 3 + kx];
            }
            #pragma unroll
            for (int p = 0; p < 4; p++) part[c * 20 + g * 4 + p] = acc[p >> 1][p & 1];
        }
        __syncthreads();
        if (tid < 50) {
            int c = tid;
            float a00 = b3[c], a01 = 0.f, a10 = 0.f, a11 = 0.f;
            a00 += part[c*20+0]; a01 += part[c*20+1]; a10 += part[c*20+2]; a11 += part[c*20+3];
            #pragma unroll
            for (int g = 1; g < 5; g++) {
                a00 += part[c*20+g*4+0]; a01 += part[c*20+g*4+1];
                a10 += part[c*20+g*4+2]; a11 += part[c*20+g*4+3];
            }
            float m = fmaxf(fmaxf(a00, a01), fmaxf(a10, a11));
            g_c32[b * 50 + c] = fmaxf(m, 0.f);
        }
    } else {
        // ---- l12: Linear(5->500) + pool(3,3) -> [50,166] ----
        __shared__ float swl[2500];
        __shared__ float sbl[500];
        for (int i = tid; i < 2500; i += 256) swl[i] = lw[i];
        for (int i = tid; i < 500; i += 256) sbl[i] = lb[i];
        __syncthreads();
        for (int o = tid; o < L12_PER_B; o += 256) {
            int c = o / 166, t = o % 166;
            const float* hc = s2 + c * 25;
            float m = -1e30f;
            #pragma unroll
            for (int i = 0; i < 3; i++) {
                #pragma unroll
                for (int dj = 0; dj < 3; dj++) {
                    int j = 3 * t + dj;
                    float a = sbl[j];
                    #pragma unroll
                    for (int k = 0; k < 5; k++) a += hc[i * 5 + k] * swl[j * 5 + k];
                    m = fmaxf(m, a);
                }
            }
            g_l12[b * L12_PER_B + o] = m;
        }
    }
}

// ---------------- merged heads: one kernel for l11 / l12 / c32 / c3d ----------------
// out rows: l11 0..499 | l12 500..665 | c32 666 | c3d 667..691
__global__ void __launch_bounds__(256) k_heads(
        const float* __restrict__ l1w, const float* __restrict__ l1b,
        const float* __restrict__ l2w, const float* __restrict__ l2b,
        float* __restrict__ out) {
    int b = blockIdx.y;
    int tid = threadIdx.x, lane = tid & 31, r = tid >> 5;   // 8 rows/block
    int d1 = g_d1[b];

    int nrows, rowbase, mode;   // mode: 0=l11(affine), 1=l12, 2=c32, 3=c3d
    if (d1 == 2)      { mode = 0; nrows = 500; rowbase = 0; }
    else if (d1 == 1) { mode = 3; nrows = 25;  rowbase = 667; }
    else if (g_d2[b] == 0) { mode = 2; nrows = 1;   rowbase = 666; }
    else                   { mode = 1; nrows = 166; rowbase = 500; }
    if (blockIdx.x * 8 >= nrows) return;

    __shared__ float sl2[500 * 11];   // l2_w transposed, stride 11 (conflict-free)
    __shared__ float slog[8][10];
    for (int i = tid; i < 5000; i += 256) {
        int m = i / 10, l = i % 10;
        sl2[m * 11 + l] = l2w[l * 500 + m];
    }
    int gr = blockIdx.x * 8 + r;

    float acc[10];
    #pragma unroll
    for (int l = 0; l < 10; l++) acc[l] = 0.f;

    if (mode == 0) {
        // ---- affine l11 path: h = relu(p*A[s] + C[s]) ----
        __syncthreads();
        bool act = (gr < 500);
        int s_ = act ? (gr % 10) : 0;
        int c_ = act ? (gr / 10) : 0;
        float p = act ? g_p7[b * 50 + c_] : 0.f;
        const float* Ap = g_A + s_ * 500;
        const float* Cp = g_C + s_ * 500;
        for (int m = lane; m < 500; m += 32) {
            float h = fmaxf(fmaf(p, __ldg(Ap + m), __ldg(Cp + m)), 0.f);
            #pragma unroll
            for (int l = 0; l < 10; l++) acc[l] += h * sl2[m * 11 + l];
        }
    } else {
        // ---- generic path ----
        const float* src;
        int perb;
        if (mode == 1)      { src = g_l12; perb = L12_PER_B; }
        else if (mode == 2) { src = g_c32; perb = 50; }
        else                { src = g_c3d; perb = H2_PER_B; }

        __shared__ float4 sl1c4[64 * 13];             // l1_w chunk, 52-float rows (16B aligned)
        float* sl1c = (float*)sl1c4;
        __shared__ float sbias[500];
        __shared__ float4 sv4[8 * 13];                // 8 rows x 52 (padded)
        float* sv = (float*)sv4;
        for (int i = tid; i < 500; i += 256) sbias[i] = l1b[i];
        int rows_here = nrows - blockIdx.x * 8;
        if (rows_here > 8) rows_here = 8;
        for (int i = tid; i < 8 * 52; i += 256) {
            int rr = i / 52, k = i % 52;
            sv[i] = (rr < rows_here && k < 50)
                ? src[(size_t)b * perb + (blockIdx.x * 8 + rr) * 50 + k] : 0.f;
        }
        __syncthreads();
        float4 vr4[13];
        #pragma unroll
        for (int j = 0; j < 13; j++) vr4[j] = sv4[r * 13 + j];
        for (int m0 = 0; m0 < 500; m0 += 64) {
            int cnt = 500 - m0; if (cnt > 64) cnt = 64;
            __syncthreads();
            for (int i = tid; i < cnt * 52; i += 256) {
                int mm = i / 52, k = i % 52;
                sl1c[mm * 52 + k] = (k < 50) ? l1w[(m0 + mm) * 50 + k] : 0.f;
            }
            __syncthreads();
            for (int mm = lane; mm < cnt; mm += 32) {
                int m = m0 + mm;
                float h = sbias[m];
                const float4* w4 = (const float4*)(sl1c + mm * 52);
                #pragma unroll
                for (int j = 0; j < 13; j++) {
                    float4 w = w4[j];
                    float4 v = vr4[j];
                    h += v.x * w.x;
                    h += v.y * w.y;
                    h += v.z * w.z;
                    h += v.w * w.w;
                }
                h = fmaxf(h, 0.f);
                #pragma unroll
                for (int l = 0; l < 10; l++) acc[l] += h * sl2[m * 11 + l];
            }
        }
    }

    #pragma unroll
    for (int off = 16; off; off >>= 1)
        #pragma unroll
        for (int l = 0; l < 10; l++) acc[l] += __shfl_down_sync(0xffffffffu, acc[l], off);
    if (lane == 0) {
        #pragma unroll
        for (int l = 0; l < 10; l++) slog[r][l] = acc[l] + l2b[l];
    }
    __syncthreads();
    if (tid < 8) {
        int grr = blockIdx.x * 8 + tid;
        if (grr < nrows) {
            float z[10], mx = -1e30f;
            #pragma unroll
            for (int l = 0; l < 10; l++) { z[l] = slog[tid][l]; mx = fmaxf(mx, z[l]); }
            float se = 0.f;
            #pragma unroll
            for (int l = 0; l < 10; l++) se += expf(z[l] - mx);
            float lse = mx + logf(se);
            float* o = out + (size_t)b * OUT_PER_B + (rowbase + grr) * 10;
            #pragma unroll
            for (int l = 0; l < 10; l++) o[l] = z[l] - lse;
        }
    }
}

// ---------------- optional d1/d2 outputs (cast to float) ----------------
__global__ void k_write_dx(float* __restrict__ out, int wd1, int wd2) {
    int i = blockIdx.x * blockDim.x + threadIdx.x;
    if (i < BATCH) {
        if (wd1) out[(size_t)BATCH * OUT_PER_B + i] = (float)g_d1[i];
        if (wd2) out[(size_t)BATCH * OUT_PER_B + BATCH + i] = (float)g_d2[i];
    }
}

extern "C" void kernel_launch(void* const* d_in, const int* in_sizes, int n_in,
                              void* d_out, int out_size) {
    const float* x     = (const float*)d_in[0];
    const float* c1w   = (const float*)d_in[1];
    const float* c1b   = (const float*)d_in[2];
    const float* c2w   = (const float*)d_in[3];
    const float* c2b   = (const float*)d_in[4];
    const float* c3w   = (const float*)d_in[5];
    const float* c3b   = (const float*)d_in[6];
    const float* l1w   = (const float*)d_in[7];
    const float* l1b   = (const float*)d_in[8];
    const float* l2w   = (const float*)d_in[9];
    const float* l2b   = (const float*)d_in[10];
    const float* d1w   = (const float*)d_in[11];
    const float* d1b   = (const float*)d_in[12];
    const float* d2w   = (const float*)d_in[13];
    const float* d2b   = (const float*)d_in[14];
    const float* c1c3w = (const float*)d_in[15];
    const float* c1c3b = (const float*)d_in[16];
    const float* c1l1w = (const float*)d_in[17];
    const float* c1l1b = (const float*)d_in[18];
    const float* c2l1w = (const float*)d_in[19];
    const float* c2l1b = (const float*)d_in[20];
    float* out = (float*)d_out;

    cudaMemsetAsync(d_out, 0, (size_t)out_size * sizeof(float), 0);

    k_precompAC<<<10, 500>>>(c1l1w, c1l1b, l1w, l1b);
    k_stage12<<<BATCH, 256>>>(x, c1w, c1b, d1w, d1b, c2w, c2b, d2w, d2b);
    k_branch<<<BATCH, 256>>>(c1c3w, c1c3b, c3w, c3b, c2l1w, c2l1b);
    k_heads<<<dim3(63, BATCH), 256>>>(l1w, l1b, l2w, l2b, out);

    long long base = (long long)BATCH * OUT_PER_B;
    int wd1 = (out_size >= base + BATCH) ? 1 : 0;
    int wd2 = (out_size >= base + 2 * BATCH) ? 1 : 0;
    if (wd1 || wd2) k_write_dx<<<2, 256>>>(out, wd1, wd2);
}

// round 14
// speedup vs baseline: 1.0673x; 1.0624x over previous
#include <cuda_runtime.h>
#include <math.h>

#define BATCH 512
#define H1_PER_B 8450   // 50*13*13
#define H2_PER_B 1250   // 50*5*5
#define L12_PER_B 8300  // 50*166
#define OUT_PER_B 6920  // 692*10

// ---------------- scratch (device globals; no runtime alloc) ----------------
__device__ float g_h1[BATCH * H1_PER_B];
__device__ float g_p7[BATCH * 50];
__device__ int   g_d1[BATCH];
__device__ float g_h2[BATCH * H2_PER_B];
__device__ int   g_d2[BATCH];
__device__ float g_c32[BATCH * 50];
__device__ float g_c3d[BATCH * H2_PER_B];
__device__ float g_l12[BATCH * L12_PER_B];
__device__ float g_A[10 * 500];
__device__ float g_C[10 * 500];
__device__ float4 g_l2t4[1376];       // l2_w transposed, stride-11 rows, padded to 5504 floats

// ---------------- precompute affine l11-head factors ----------------
__global__ void k_precompAC(const float* __restrict__ c1l1w, const float* __restrict__ c1l1b,
                            const float* __restrict__ l1w, const float* __restrict__ l1b) {
    int s = blockIdx.x;       // 0..9
    int m = threadIdx.x;      // 0..499
    float a = 0.f, c = 0.f;
    const float* wrow = l1w + m * 50;
    #pragma unroll
    for (int k = 0; k < 50; k++) {
        float lw = wrow[k];
        a += c1l1w[s * 50 + k] * lw;
        c += c1l1b[s * 50 + k] * lw;
    }
    g_A[s * 500 + m] = a;
    g_C[s * 500 + m] = c + l1b[m];
}

// ---------------- one-time transpose of l2_w into stride-11 layout ----------------
// block l (0..9), thread m (0..499): coalesced read, one-time scatter write.
__global__ void k_l2t(const float* __restrict__ l2w) {
    int l = blockIdx.x;
    int m = threadIdx.x;
    float* g_l2t = (float*)g_l2t4;
    g_l2t[m * 11 + l] = l2w[l * 500 + m];
    if (l == 0) {
        g_l2t[m * 11 + 10] = 0.f;                 // pad column
        if (m < 4) g_l2t[5500 + m] = 0.f;         // tail pad
    }
}

// ---------------- conv 50->50 3x3 on 13x13 (+relu+pool2 -> 5x5), input in smem ----------------
__device__ __forceinline__ void conv50_pool(const float* __restrict__ s,
                                            const float* __restrict__ w,
                                            const float* __restrict__ bias,
                                            float* __restrict__ out, int tid) {
    if (tid < 250) {
        int c = tid / 5, py = tid % 5;
        float bc = bias[c];
        float acc[2][10];
        #pragma unroll
        for (int r = 0; r < 2; r++)
            #pragma unroll
            for (int xx = 0; xx < 10; xx++) acc[r][xx] = bc;
        const float* wc = w + c * 450;
        for (int ci = 0; ci < 50; ci++) {
            float win[4][12];
            const float* sc = s + ci * 169 + (2 * py) * 13;
            #pragma unroll
            for (int r = 0; r < 4; r++)
                #pragma unroll
                for (int xx = 0; xx < 12; xx++) win[r][xx] = sc[r * 13 + xx];
            float wv[9];
            #pragma unroll
            for (int k = 0; k < 9; k++) wv[k] = __ldg(wc + ci * 9 + k);
            #pragma unroll
            for (int r = 0; r < 2; r++)
                #pragma unroll
                for (int ky = 0; ky < 3; ky++)
                    #pragma unroll
                    for (int kx = 0; kx < 3; kx++)
                        #pragma unroll
                        for (int xx = 0; xx < 10; xx++)
                            acc[r][xx] += win[r + ky][xx + kx] * wv[ky * 3 + kx];
        }
        #pragma unroll
        for (int px = 0; px < 5; px++) {
            float m = fmaxf(fmaxf(acc[0][2 * px], acc[0][2 * px + 1]),
                            fmaxf(acc[1][2 * px], acc[1][2 * px + 1]));
            out[c * 25 + py * 5 + px] = fmaxf(m, 0.f);
        }
    }
}

// ---------------- fused stage 1+2: conv1+relu+pool2, d1, pool7, conv2+relu+pool2, d2 ----------------
__global__ void __launch_bounds__(256) k_stage12(
        const float* __restrict__ x, const float* __restrict__ w1,
        const float* __restrict__ b1,
        const float* __restrict__ d1w, const float* __restrict__ d1b,
        const float* __restrict__ w2, const float* __restrict__ b2,
        const float* __restrict__ d2w, const float* __restrict__ d2b) {
    int b = blockIdx.x;
    int tid = threadIdx.x;
    __shared__ float sx[784];
    __shared__ float sw[450];
    __shared__ float sb[50];
    __shared__ float sh1[8450];
    __shared__ float sh2[1250];
    __shared__ int   sp7[50];          // channel max bits (values >= 0)
    __shared__ float r0[8], r1[8], r2[8];
    const float* xb = x + b * 784;
    for (int i = tid; i < 784; i += 256) sx[i] = xb[i];
    for (int i = tid; i < 450; i += 256) sw[i] = w1[i];
    for (int i = tid; i < 50; i += 256) { sb[i] = b1[i]; sp7[i] = 0; }
    __syncthreads();

    float* h1g = g_h1 + b * H1_PER_B;
    float a0 = 0.f, a1 = 0.f, a2 = 0.f;
    for (int o = tid; o < 8450; o += 256) {
        int c = o / 169, p = o % 169, py = p / 13, px = p % 13;
        const float* wc = sw + c * 9;
        float m = 0.f;
        #pragma unroll
        for (int dy = 0; dy < 2; dy++) {
            #pragma unroll
            for (int dx = 0; dx < 2; dx++) {
                int cy = 2 * py + dy, cx = 2 * px + dx;
                float acc = sb[c];
                #pragma unroll
                for (int ky = 0; ky < 3; ky++)
                    #pragma unroll
                    for (int kx = 0; kx < 3; kx++)
                        acc += sx[(cy + ky) * 28 + cx + kx] * wc[ky * 3 + kx];
                m = fmaxf(m, acc);
            }
        }
        sh1[o] = m;
        h1g[o] = m;
        a0 += m * d1w[o];
        a1 += m * d1w[8450 + o];
        a2 += m * d1w[16900 + o];
        if (py < 7 && px < 7) atomicMax(&sp7[c], __float_as_int(m));
    }
    #pragma unroll
    for (int o = 16; o; o >>= 1) {
        a0 += __shfl_down_sync(0xffffffffu, a0, o);
        a1 += __shfl_down_sync(0xffffffffu, a1, o);
        a2 += __shfl_down_sync(0xffffffffu, a2, o);
    }
    if ((tid & 31) == 0) { r0[tid >> 5] = a0; r1[tid >> 5] = a1; r2[tid >> 5] = a2; }
    __syncthreads();
    if (tid == 0) {
        float l0 = d1b[0], l1 = d1b[1], l2 = d1b[2];
        for (int w_ = 0; w_ < 8; w_++) { l0 += r0[w_]; l1 += r1[w_]; l2 += r2[w_]; }
        int d = 0; float best = l0;
        if (l1 > best) { best = l1; d = 1; }
        if (l2 > best) { best = l2; d = 2; }
        g_d1[b] = d;
    }
    for (int c = tid; c < 50; c += 256)
        g_p7[b * 50 + c] = __int_as_float(sp7[c]);

    conv50_pool(sh1, w2, b2, sh2, tid);
    __syncthreads();
    float* o2 = g_h2 + b * H2_PER_B;
    float c0 = 0.f, c1 = 0.f;
    for (int i = tid; i < 1250; i += 256) {
        float v = sh2[i];
        o2[i] = v;
        c0 += v * d2w[i];
        c1 += v * d2w[1250 + i];
    }
    #pragma unroll
    for (int off = 16; off; off >>= 1) {
        c0 += __shfl_down_sync(0xffffffffu, c0, off);
        c1 += __shfl_down_sync(0xffffffffu, c1, off);
    }
    if ((tid & 31) == 0) { r0[tid >> 5] = c0; r1[tid >> 5] = c1; }
    __syncthreads();
    if (tid == 0) {
        float s0 = d2b[0], s1 = d2b[1];
        for (int w_ = 0; w_ < 8; w_++) { s0 += r0[w_]; s1 += r1[w_]; }
        g_d2[b] = (s1 > s0) ? 1 : 0;
    }
}

// ---------------- merged branch kernel: per sample exactly one of c3d / c32 / l12 ----------------
__global__ void __launch_bounds__(256) k_branch(
        const float* __restrict__ cw, const float* __restrict__ cb,     // c1c3 (13->13)
        const float* __restrict__ w3, const float* __restrict__ b3,     // conv3
        const float* __restrict__ lw, const float* __restrict__ lb) {   // c2l1 (5->500)
    int b = blockIdx.x;
    int tid = threadIdx.x;
    int d1 = g_d1[b];
    if (d1 == 2) return;

    if (d1 == 1) {
        // ---- c3d: Linear(13->13) on h1 rows, conv3+relu+pool2 -> g_c3d ----
        __shared__ float s[8450];
        __shared__ float swl[169];
        __shared__ float sbl[13];
        if (tid < 169) swl[tid] = cw[tid];
        if (tid < 13) sbl[tid] = cb[tid];
        __syncthreads();
        const float* h = g_h1 + b * H1_PER_B;
        for (int o = tid; o < 8450; o += 256) {
            int row = o / 13, j = o % 13;
            const float* hr = h + row * 13;
            float a = sbl[j];
            #pragma unroll
            for (int k = 0; k < 13; k++) a += hr[k] * swl[j * 13 + k];
            s[o] = a;
        }
        __syncthreads();
        conv50_pool(s, w3, b3, g_c3d + b * H2_PER_B, tid);
        return;
    }

    // d1 == 0 paths need h2 in smem
    __shared__ float s2[1250];
    for (int i = tid; i < 1250; i += 256) s2[i] = g_h2[b * H2_PER_B + i];

    if (g_d2[b] == 0) {
        // ---- c32: conv3 on 5x5 + relu + pool2 -> [50]; ci split over 5 groups ----
        __shared__ float part[50 * 5 * 4];
        __syncthreads();
        if (tid < 250) {
            int c = tid / 5, g = tid % 5;
            float acc[2][2];
            acc[0][0] = acc[0][1] = acc[1][0] = acc[1][1] = 0.f;
            const float* wc = w3 + c * 450;
            for (int ci = g * 10; ci < g * 10 + 10; ci++) {
                float win[4][4];
                const float* sc = s2 + ci * 25;
                #pragma unroll
                for (int r = 0; r < 4; r++)
                    #pragma unroll
                    for (int xx = 0; xx < 4; xx++) win[r][xx] = sc[r * 5 + xx];
                float wv[9];
                #pragma unroll
                for (int k = 0; k < 9; k++) wv[k] = __ldg(wc + ci * 9 + k);
                #pragma unroll
                for (int py = 0; py < 2; py++)
                    #pragma unroll
                    for (int px = 0; px < 2; px++)
                        #pragma unroll
                        for (int ky = 0; ky < 3; ky++)
                            #pragma unroll
                            for (int kx = 0; kx < 3; kx++)
                                acc[py][px] += win[py + ky][px + kx] * wv[ky * 3 + kx];
            }
            #pragma unroll
            for (int p = 0; p < 4; p++) part[c * 20 + g * 4 + p] = acc[p >> 1][p & 1];
        }
        __syncthreads();
        if (tid < 50) {
            int c = tid;
            float a00 = b3[c], a01 = 0.f, a10 = 0.f, a11 = 0.f;
            a00 += part[c*20+0]; a01 += part[c*20+1]; a10 += part[c*20+2]; a11 += part[c*20+3];
            #pragma unroll
            for (int g = 1; g < 5; g++) {
                a00 += part[c*20+g*4+0]; a01 += part[c*20+g*4+1];
                a10 += part[c*20+g*4+2]; a11 += part[c*20+g*4+3];
            }
            float m = fmaxf(fmaxf(a00, a01), fmaxf(a10, a11));
            g_c32[b * 50 + c] = fmaxf(m, 0.f);
        }
    } else {
        // ---- l12: Linear(5->500) + pool(3,3) -> [50,166] ----
        __shared__ float swl[2500];
        __shared__ float sbl[500];
        for (int i = tid; i < 2500; i += 256) swl[i] = lw[i];
        for (int i = tid; i < 500; i += 256) sbl[i] = lb[i];
        __syncthreads();
        for (int o = tid; o < L12_PER_B; o += 256) {
            int c = o / 166, t = o % 166;
            const float* hc = s2 + c * 25;
            float m = -1e30f;
            #pragma unroll
            for (int i = 0; i < 3; i++) {
                #pragma unroll
                for (int dj = 0; dj < 3; dj++) {
                    int j = 3 * t + dj;
                    float a = sbl[j];
                    #pragma unroll
                    for (int k = 0; k < 5; k++) a += hc[i * 5 + k] * swl[j * 5 + k];
                    m = fmaxf(m, a);
                }
            }
            g_l12[b * L12_PER_B + o] = m;
        }
    }
}

// ---------------- merged heads: one kernel for l11 / l12 / c32 / c3d ----------------
// out rows: l11 0..499 | l12 500..665 | c32 666 | c3d 667..691
__global__ void __launch_bounds__(256) k_heads(
        const float* __restrict__ l1w, const float* __restrict__ l1b,
        const float* __restrict__ l2b,
        float* __restrict__ out) {
    int b = blockIdx.y;
    int tid = threadIdx.x, lane = tid & 31, r = tid >> 5;   // 8 rows/block
    int d1 = g_d1[b];

    int nrows, rowbase, mode;   // mode: 0=l11(affine), 1=l12, 2=c32, 3=c3d
    if (d1 == 2)      { mode = 0; nrows = 500; rowbase = 0; }
    else if (d1 == 1) { mode = 3; nrows = 25;  rowbase = 667; }
    else if (g_d2[b] == 0) { mode = 2; nrows = 1;   rowbase = 666; }
    else                   { mode = 1; nrows = 166; rowbase = 500; }
    if (blockIdx.x * 8 >= nrows) return;

    __shared__ float4 sl2_4[1376];    // l2_w transposed, stride-11 (conflict-free), 5504 floats
    float* sl2 = (float*)sl2_4;
    __shared__ float slog[8][10];
    // coalesced float4 copy from the pre-transposed table (was: 32-way-replay strided LDG)
    for (int i = tid; i < 1376; i += 256) sl2_4[i] = g_l2t4[i];
    int gr = blockIdx.x * 8 + r;

    float acc[10];
    #pragma unroll
    for (int l = 0; l < 10; l++) acc[l] = 0.f;

    if (mode == 0) {
        // ---- affine l11 path: h = relu(p*A[s] + C[s]) ----
        __syncthreads();
        bool act = (gr < 500);
        int s_ = act ? (gr % 10) : 0;
        int c_ = act ? (gr / 10) : 0;
        float p = act ? g_p7[b * 50 + c_] : 0.f;
        const float* Ap = g_A + s_ * 500;
        const float* Cp = g_C + s_ * 500;
        for (int m = lane; m < 500; m += 32) {
            float h = fmaxf(fmaf(p, __ldg(Ap + m), __ldg(Cp + m)), 0.f);
            #pragma unroll
            for (int l = 0; l < 10; l++) acc[l] += h * sl2[m * 11 + l];
        }
    } else {
        // ---- generic path ----
        const float* src;
        int perb;
        if (mode == 1)      { src = g_l12; perb = L12_PER_B; }
        else if (mode == 2) { src = g_c32; perb = 50; }
        else                { src = g_c3d; perb = H2_PER_B; }

        __shared__ float4 sl1c4[64 * 13];             // l1_w chunk, 52-float rows (16B aligned)
        float* sl1c = (float*)sl1c4;
        __shared__ float sbias[500];
        __shared__ float4 sv4[8 * 13];                // 8 rows x 52 (padded)
        float* sv = (float*)sv4;
        for (int i = tid; i < 500; i += 256) sbias[i] = l1b[i];
        int rows_here = nrows - blockIdx.x * 8;
        if (rows_here > 8) rows_here = 8;
        for (int i = tid; i < 8 * 52; i += 256) {
            int rr = i / 52, k = i % 52;
            sv[i] = (rr < rows_here && k < 50)
                ? src[(size_t)b * perb + (blockIdx.x * 8 + rr) * 50 + k] : 0.f;
        }
        __syncthreads();
        float4 vr4[13];
        #pragma unroll
        for (int j = 0; j < 13; j++) vr4[j] = sv4[r * 13 + j];
        for (int m0 = 0; m0 < 500; m0 += 64) {
            int cnt = 500 - m0; if (cnt > 64) cnt = 64;
            __syncthreads();
            for (int i = tid; i < cnt * 52; i += 256) {
                int mm = i / 52, k = i % 52;
                sl1c[mm * 52 + k] = (k < 50) ? l1w[(m0 + mm) * 50 + k] : 0.f;
            }
            __syncthreads();
            for (int mm = lane; mm < cnt; mm += 32) {
                int m = m0 + mm;
                float h = sbias[m];
                const float4* w4 = (const float4*)(sl1c + mm * 52);
                #pragma unroll
                for (int j = 0; j < 13; j++) {
                    float4 w = w4[j];
                    float4 v = vr4[j];
                    h += v.x * w.x;
                    h += v.y * w.y;
                    h += v.z * w.z;
                    h += v.w * w.w;
                }
                h = fmaxf(h, 0.f);
                #pragma unroll
                for (int l = 0; l < 10; l++) acc[l] += h * sl2[m * 11 + l];
            }
        }
    }

    #pragma unroll
    for (int off = 16; off; off >>= 1)
        #pragma unroll
        for (int l = 0; l < 10; l++) acc[l] += __shfl_down_sync(0xffffffffu, acc[l], off);
    if (lane == 0) {
        #pragma unroll
        for (int l = 0; l < 10; l++) slog[r][l] = acc[l] + l2b[l];
    }
    __syncthreads();
    if (tid < 8) {
        int grr = blockIdx.x * 8 + tid;
        if (grr < nrows) {
            float z[10], mx = -1e30f;
            #pragma unroll
            for (int l = 0; l < 10; l++) { z[l] = slog[tid][l]; mx = fmaxf(mx, z[l]); }
            float se = 0.f;
            #pragma unroll
            for (int l = 0; l < 10; l++) se += expf(z[l] - mx);
            float lse = mx + logf(se);
            float* o = out + (size_t)b * OUT_PER_B + (rowbase + grr) * 10;
            #pragma unroll
            for (int l = 0; l < 10; l++) o[l] = z[l] - lse;
        }
    }
}

// ---------------- optional d1/d2 outputs (cast to float) ----------------
__global__ void k_write_dx(float* __restrict__ out, int wd1, int wd2) {
    int i = blockIdx.x * blockDim.x + threadIdx.x;
    if (i < BATCH) {
        if (wd1) out[(size_t)BATCH * OUT_PER_B + i] = (float)g_d1[i];
        if (wd2) out[(size_t)BATCH * OUT_PER_B + BATCH + i] = (float)g_d2[i];
    }
}

extern "C" void kernel_launch(void* const* d_in, const int* in_sizes, int n_in,
                              void* d_out, int out_size) {
    const float* x     = (const float*)d_in[0];
    const float* c1w   = (const float*)d_in[1];
    const float* c1b   = (const float*)d_in[2];
    const float* c2w   = (const float*)d_in[3];
    const float* c2b   = (const float*)d_in[4];
    const float* c3w   = (const float*)d_in[5];
    const float* c3b   = (const float*)d_in[6];
    const float* l1w   = (const float*)d_in[7];
    const float* l1b   = (const float*)d_in[8];
    const float* l2w   = (const float*)d_in[9];
    const float* l2b   = (const float*)d_in[10];
    const float* d1w   = (const float*)d_in[11];
    const float* d1b   = (const float*)d_in[12];
    const float* d2w   = (const float*)d_in[13];
    const float* d2b   = (const float*)d_in[14];
    const float* c1c3w = (const float*)d_in[15];
    const float* c1c3b = (const float*)d_in[16];
    const float* c1l1w = (const float*)d_in[17];
    const float* c1l1b = (const float*)d_in[18];
    const float* c2l1w = (const float*)d_in[19];
    const float* c2l1b = (const float*)d_in[20];
    float* out = (float*)d_out;

    cudaMemsetAsync(d_out, 0, (size_t)out_size * sizeof(float), 0);

    k_precompAC<<<10, 500>>>(c1l1w, c1l1b, l1w, l1b);
    k_l2t<<<10, 500>>>(l2w);
    k_stage12<<<BATCH, 256>>>(x, c1w, c1b, d1w, d1b, c2w, c2b, d2w, d2b);
    k_branch<<<BATCH, 256>>>(c1c3w, c1c3b, c3w, c3b, c2l1w, c2l1b);
    k_heads<<<dim3(63, BATCH), 256>>>(l1w, l1b, l2b, out);

    long long base = (long long)BATCH * OUT_PER_B;
    int wd1 = (out_size >= base + BATCH) ? 1 : 0;
    int wd2 = (out_size >= base + 2 * BATCH) ? 1 : 0;
    if (wd1 || wd2) k_write_dx<<<2, 256>>>(out, wd1, wd2);
}